// round 14
// baseline (speedup 1.0000x reference)
#include <cuda_runtime.h>
#include <math.h>

// ---------------------------------------------------------------------------
// EnhancedBoundaryAttnPool — fp32 baseline (R9: fix boundaries dtype)
// B=16, T=2048, K=128, H=1024, NH=8, d=128
// ---------------------------------------------------------------------------

#define cB  16
#define cT  2048
#define cK  128
#define cH  1024
#define cNH 8
#define cD  128
#define BT  (cB * cT)   // 32768
#define BKR (cB * cK)   // 2048 slot rows
#define INV_SQRT_D 0.08838834764831845f

// ------------------------- scratch (device globals) -------------------------
__device__ float d_init [(size_t)BKR * cH];
__device__ float d_q    [(size_t)BKR * cH];
__device__ float d_qh   [(size_t)BKR * cH];
__device__ float d_kv   [(size_t)BT * 2 * cH];   // 268 MB: [kh | vh] per token
__device__ float d_ctx1 [(size_t)BKR * cH];
__device__ float d_slots[(size_t)BKR * cH];
__device__ float d_qkv  [(size_t)BKR * 3 * cH];
__device__ float d_tmp  [(size_t)BKR * cH];
__device__ float d_ctx2 [(size_t)BKR * cH];
__device__ int   d_bnds [2 * BKR];               // normalized int32 [s,e] pairs

// ------------------------ boundary dtype normalization ----------------------
// Reference does .astype(jnp.int64) but JAX default x64=off keeps int32.
// Robust to both: int64 little-endian values (<=2048) have every odd int32
// word == 0; int32 data has odd words = ends >= 1. raw[1]==0  <=>  int64.
__global__ __launch_bounds__(256) void conv_bounds_k(
    const int* __restrict__ raw, int* __restrict__ outb)
{
    int i = blockIdx.x * 256 + threadIdx.x;
    if (i >= 2 * BKR) return;
    bool is64 = (raw[1] == 0);
    outb[i] = is64 ? raw[2 * i] : raw[i];
}

// ------------------------------ init slots ---------------------------------
// one block per (b,k): mean of projected[b, start:end, :]
__global__ __launch_bounds__(256) void init_slots_k(
    const float* __restrict__ proj, const int* __restrict__ bounds,
    const float* __restrict__ smask, float* __restrict__ outs)
{
    int bk = blockIdx.x;
    int b = bk >> 7;
    int start = bounds[2 * bk];
    int end   = bounds[2 * bk + 1];
    if (start < 0) start = 0;
    if (end > cT) end = cT;
    float mv = smask[bk];
    int col = threadIdx.x << 2;              // 256 threads x 4 floats = 1024
    float4 acc = make_float4(0.f, 0.f, 0.f, 0.f);
    int cnt = 0;
    if (mv > 0.f) {
        const float* base = proj + (size_t)b * cT * cH + col;
        for (int t = start; t < end; t++) {
            float4 v = *(const float4*)(base + (size_t)t * cH);
            acc.x += v.x; acc.y += v.y; acc.z += v.z; acc.w += v.w;
        }
        cnt = end - start;
        if (cnt < 0) cnt = 0;
    }
    float w = 1.f / (float)(cnt < 1 ? 1 : cnt);
    acc.x *= w; acc.y *= w; acc.z *= w; acc.w *= w;
    *(float4*)(outs + (size_t)bk * cH + col) = acc;
}

// ------------------------------ SGEMM (NT) ----------------------------------
// C[M,N] = A[M,Kd] @ W[N,Kd]^T + bias[N]; M,N multiples of 128, Kd of 16
#define GBM 128
#define GBN 128
#define GBK 16

__global__ __launch_bounds__(256) void sgemm_nt_bias(
    const float* __restrict__ A, const float* __restrict__ W,
    const float* __restrict__ bias, float* __restrict__ C,
    int M, int N, int Kd)
{
    __shared__ __align__(16) float As[GBK][GBM];
    __shared__ __align__(16) float Bs[GBK][GBN];
    const int bn = blockIdx.x, bm = blockIdx.y;
    const int tid = threadIdx.x;
    const int tr = tid >> 4;             // 0..15
    const int tc = tid & 15;             // 0..15
    const int lr = tid >> 2;             // 0..63 (load row)
    const int lc = (tid & 3) << 2;       // 0,4,8,12 (load col)
    const float* Ab = A + (size_t)bm * GBM * Kd + lc;
    const float* Wb = W + (size_t)bn * GBN * Kd + lc;

    float acc[8][8];
    #pragma unroll
    for (int i = 0; i < 8; i++)
        #pragma unroll
        for (int j = 0; j < 8; j++) acc[i][j] = 0.f;

    for (int k0 = 0; k0 < Kd; k0 += GBK) {
        #pragma unroll
        for (int half = 0; half < 2; half++) {
            int r = lr + half * 64;
            float4 va = *(const float4*)(Ab + (size_t)r * Kd + k0);
            As[lc + 0][r] = va.x; As[lc + 1][r] = va.y;
            As[lc + 2][r] = va.z; As[lc + 3][r] = va.w;
            float4 vb = *(const float4*)(Wb + (size_t)r * Kd + k0);
            Bs[lc + 0][r] = vb.x; Bs[lc + 1][r] = vb.y;
            Bs[lc + 2][r] = vb.z; Bs[lc + 3][r] = vb.w;
        }
        __syncthreads();
        #pragma unroll
        for (int kk = 0; kk < GBK; kk++) {
            float4 a0 = *(const float4*)&As[kk][tr * 8];
            float4 a1 = *(const float4*)&As[kk][tr * 8 + 4];
            float4 b0 = *(const float4*)&Bs[kk][tc * 8];
            float4 b1 = *(const float4*)&Bs[kk][tc * 8 + 4];
            float af[8] = {a0.x, a0.y, a0.z, a0.w, a1.x, a1.y, a1.z, a1.w};
            float bf[8] = {b0.x, b0.y, b0.z, b0.w, b1.x, b1.y, b1.z, b1.w};
            #pragma unroll
            for (int i = 0; i < 8; i++)
                #pragma unroll
                for (int j = 0; j < 8; j++)
                    acc[i][j] = fmaf(af[i], bf[j], acc[i][j]);
        }
        __syncthreads();
    }

    #pragma unroll
    for (int i = 0; i < 8; i++) {
        size_t row = (size_t)bm * GBM + tr * 8 + i;
        #pragma unroll
        for (int j = 0; j < 8; j += 4) {
            int col = bn * GBN + tc * 8 + j;
            float4 o;
            o.x = acc[i][j + 0] + bias[col + 0];
            o.y = acc[i][j + 1] + bias[col + 1];
            o.z = acc[i][j + 2] + bias[col + 2];
            o.w = acc[i][j + 3] + bias[col + 3];
            *(float4*)(C + row * N + col) = o;
        }
    }
}

// --------------------------- cross attention -------------------------------
// one block per (b,k); warp = head; lane = window token (W <= 32)
__global__ __launch_bounds__(256) void cross_attn_k(
    const float* __restrict__ qh, const float* __restrict__ kv,
    const int* __restrict__ bounds, const float* __restrict__ smask,
    float* __restrict__ outc)
{
    int bk = blockIdx.x;
    int b = bk >> 7;
    int tid = threadIdx.x;
    int lane = tid & 31, h = tid >> 5;
    int start = bounds[2 * bk];
    int end   = bounds[2 * bk + 1];
    if (start < 0) start = 0;
    if (end > cT) end = cT;
    int W = end - start;
    if (W < 0) W = 0;
    if (W > 32) W = 32;
    bool valid = smask[bk] > 0.5f;

    __shared__ __align__(16) float qsh[cH];
    for (int i = tid; i < cH; i += 256) qsh[i] = qh[(size_t)bk * cH + i];
    __syncthreads();

    float s = -INFINITY;
    if (valid && lane < W) {
        const float* kr = kv + (size_t)(b * cT + start + lane) * (2 * cH) + h * cD;
        const float* qp = qsh + h * cD;
        float a = 0.f;
        #pragma unroll
        for (int x = 0; x < cD; x += 4) {
            float4 k4 = *(const float4*)(kr + x);
            a = fmaf(qp[x + 0], k4.x, a);
            a = fmaf(qp[x + 1], k4.y, a);
            a = fmaf(qp[x + 2], k4.z, a);
            a = fmaf(qp[x + 3], k4.w, a);
        }
        s = a * INV_SQRT_D;
    }
    float mx = s;
    #pragma unroll
    for (int o = 16; o; o >>= 1) mx = fmaxf(mx, __shfl_xor_sync(0xffffffffu, mx, o));
    float p = (s == -INFINITY) ? 0.f : __expf(s - mx);
    float sum = p;
    #pragma unroll
    for (int o = 16; o; o >>= 1) sum += __shfl_xor_sync(0xffffffffu, sum, o);
    p = (sum > 0.f) ? p / sum : 0.f;

    float o0 = 0.f, o1 = 0.f, o2 = 0.f, o3 = 0.f;
    for (int t = 0; t < W; t++) {
        float pt = __shfl_sync(0xffffffffu, p, t);
        const float* vr = kv + (size_t)(b * cT + start + t) * (2 * cH) + cH + h * cD + (lane << 2);
        float4 v4 = *(const float4*)vr;
        o0 = fmaf(pt, v4.x, o0);
        o1 = fmaf(pt, v4.y, o1);
        o2 = fmaf(pt, v4.z, o2);
        o3 = fmaf(pt, v4.w, o3);
    }
    *(float4*)(outc + (size_t)bk * cH + h * cD + (lane << 2)) = make_float4(o0, o1, o2, o3);
}

// -------------------------- residual + layernorm ----------------------------
// one block per row (H=1024), out = LN(x + res) * g + b
__global__ __launch_bounds__(256) void ln_residual_k(
    const float* __restrict__ x, const float* __restrict__ res,
    const float* __restrict__ g, const float* __restrict__ bb,
    float* __restrict__ out)
{
    int row = blockIdx.x;
    int tid = threadIdx.x;
    const float* xr = x + (size_t)row * cH;
    const float* rr = res + (size_t)row * cH;
    __shared__ float red[8];

    float v[4];
    float s = 0.f;
    #pragma unroll
    for (int i = 0; i < 4; i++) {
        int c = i * 256 + tid;
        v[i] = xr[c] + rr[c];
        s += v[i];
    }
    #pragma unroll
    for (int o = 16; o; o >>= 1) s += __shfl_xor_sync(0xffffffffu, s, o);
    if ((tid & 31) == 0) red[tid >> 5] = s;
    __syncthreads();
    float m = 0.f;
    #pragma unroll
    for (int i = 0; i < 8; i++) m += red[i];
    m *= (1.f / (float)cH);
    __syncthreads();

    float q = 0.f;
    #pragma unroll
    for (int i = 0; i < 4; i++) { float d = v[i] - m; q += d * d; }
    #pragma unroll
    for (int o = 16; o; o >>= 1) q += __shfl_xor_sync(0xffffffffu, q, o);
    if ((tid & 31) == 0) red[tid >> 5] = q;
    __syncthreads();
    float var = 0.f;
    #pragma unroll
    for (int i = 0; i < 8; i++) var += red[i];
    var *= (1.f / (float)cH);
    float rstd = rsqrtf(var + 1e-5f);

    #pragma unroll
    for (int i = 0; i < 4; i++) {
        int c = i * 256 + tid;
        out[(size_t)row * cH + c] = (v[i] - m) * rstd * g[c] + bb[c];
    }
}

// ----------------------------- self attention -------------------------------
// grid (B*NH, 4): block handles 32 query rows of one (b,h); 128 threads.
// causal + pad mask, softmax over 128 keys.
__global__ __launch_bounds__(128) void self_attn_k(
    const float* __restrict__ qkv, const float* __restrict__ smask,
    float* __restrict__ outc)
{
    int bh = blockIdx.x;
    int b = bh >> 3, h = bh & 7;
    int j = threadIdx.x;
    __shared__ float qsh[cD];
    __shared__ float psh[cK];
    __shared__ float red[4];

    const size_t rs = 3 * cH;
    const float* base = qkv + (size_t)b * cK * rs;
    const float* Kp = base + cH + h * cD;
    const float* Vp = base + 2 * cH + h * cD;
    bool jvalid = smask[b * cK + j] >= 0.5f;

    int i0 = blockIdx.y * 32;
    for (int i = i0; i < i0 + 32; i++) {
        qsh[j] = base[(size_t)i * rs + h * cD + j];
        __syncthreads();
        float s = -INFINITY;
        if (j <= i && jvalid) {
            const float* kr = Kp + (size_t)j * rs;
            float a = 0.f;
            #pragma unroll 4
            for (int x = 0; x < cD; x++) a = fmaf(qsh[x], kr[x], a);
            s = a * INV_SQRT_D;
        }
        float mx = s;
        #pragma unroll
        for (int o = 16; o; o >>= 1) mx = fmaxf(mx, __shfl_xor_sync(0xffffffffu, mx, o));
        if ((j & 31) == 0) red[j >> 5] = mx;
        __syncthreads();
        mx = fmaxf(fmaxf(red[0], red[1]), fmaxf(red[2], red[3]));
        float p = (s == -INFINITY) ? 0.f : __expf(s - mx);
        float sm = p;
        #pragma unroll
        for (int o = 16; o; o >>= 1) sm += __shfl_xor_sync(0xffffffffu, sm, o);
        __syncthreads();
        if ((j & 31) == 0) red[j >> 5] = sm;
        __syncthreads();
        sm = red[0] + red[1] + red[2] + red[3];
        psh[j] = (sm > 0.f) ? p / sm : 0.f;
        __syncthreads();

        float a = 0.f;
        for (int jj = 0; jj <= i; jj++)
            a = fmaf(psh[jj], Vp[(size_t)jj * rs + j], a);
        outc[(size_t)(b * cK + i) * cH + h * cD + j] = a;
        __syncthreads();
    }
}

// ------------------------------- launcher -----------------------------------
extern "C" void kernel_launch(void* const* d_in, const int* in_sizes, int n_in,
                              void* d_out, int out_size)
{
    (void)in_sizes; (void)n_in; (void)out_size;

    const float* projected  = (const float*)d_in[0];
    const int*   bounds_raw = (const int*)d_in[1];   // int32 OR int64 view; normalized below
    const float* slot_mask  = (const float*)d_in[2];
    const float* qp_w       = (const float*)d_in[3];
    const float* qp_b       = (const float*)d_in[4];
    const float* ca_in_w    = (const float*)d_in[5];
    const float* ca_in_b    = (const float*)d_in[6];
    const float* ca_out_w   = (const float*)d_in[7];
    const float* ca_out_b   = (const float*)d_in[8];
    const float* cn_g       = (const float*)d_in[9];
    const float* cn_b       = (const float*)d_in[10];
    const float* sa_in_w    = (const float*)d_in[11];
    const float* sa_in_b    = (const float*)d_in[12];
    const float* sa_out_w   = (const float*)d_in[13];
    const float* sa_out_b   = (const float*)d_in[14];
    const float* on_g       = (const float*)d_in[15];
    const float* on_b       = (const float*)d_in[16];
    float*       out        = (float*)d_out;

    float *g_init, *g_q, *g_qh, *g_kv, *g_ctx1, *g_slots, *g_qkv, *g_tmp, *g_ctx2;
    int *g_bnds;
    cudaGetSymbolAddress((void**)&g_init,  d_init);
    cudaGetSymbolAddress((void**)&g_q,     d_q);
    cudaGetSymbolAddress((void**)&g_qh,    d_qh);
    cudaGetSymbolAddress((void**)&g_kv,    d_kv);
    cudaGetSymbolAddress((void**)&g_ctx1,  d_ctx1);
    cudaGetSymbolAddress((void**)&g_slots, d_slots);
    cudaGetSymbolAddress((void**)&g_qkv,   d_qkv);
    cudaGetSymbolAddress((void**)&g_tmp,   d_tmp);
    cudaGetSymbolAddress((void**)&g_ctx2,  d_ctx2);
    cudaGetSymbolAddress((void**)&g_bnds,  d_bnds);

    // 0) normalize boundaries (int32 vs int64, robust to either)
    conv_bounds_k<<<(2 * BKR + 255) / 256, 256>>>(bounds_raw, g_bnds);

    // 1) windowed mean pooling
    init_slots_k<<<BKR, 256>>>(projected, g_bnds, slot_mask, g_init);

    // 2) queries = init @ qp_w^T + qp_b
    sgemm_nt_bias<<<dim3(cH / GBN, BKR / GBM), 256>>>(g_init, qp_w, qp_b, g_q, BKR, cH, cH);

    // 3) qh = queries @ wq^T + bq  (ca_in_w rows [0,H))
    sgemm_nt_bias<<<dim3(cH / GBN, BKR / GBM), 256>>>(g_q, ca_in_w, ca_in_b, g_qh, BKR, cH, cH);

    // 4) kv = projected @ [wk;wv]^T + [bk;bv]  (ca_in_w rows [H,3H))  — dominant
    sgemm_nt_bias<<<dim3(2 * cH / GBN, BT / GBM), 256>>>(
        projected, ca_in_w + (size_t)cH * cH, ca_in_b + cH, g_kv, BT, 2 * cH, cH);

    // 5) windowed cross attention
    cross_attn_k<<<BKR, 256>>>(g_qh, g_kv, g_bnds, slot_mask, g_ctx1);

    // 6) attn_out = ctx1 @ ca_out_w^T + b; slots = LN(attn_out + queries)
    sgemm_nt_bias<<<dim3(cH / GBN, BKR / GBM), 256>>>(g_ctx1, ca_out_w, ca_out_b, g_tmp, BKR, cH, cH);
    ln_residual_k<<<BKR, 256>>>(g_tmp, g_q, cn_g, cn_b, g_slots);

    // 7) qkv = slots @ sa_in_w^T + sa_in_b
    sgemm_nt_bias<<<dim3(3 * cH / GBN, BKR / GBM), 256>>>(g_slots, sa_in_w, sa_in_b, g_qkv, BKR, 3 * cH, cH);

    // 8) causal self attention over slots
    self_attn_k<<<dim3(cB * cNH, 4), 128>>>(g_qkv, slot_mask, g_ctx2);

    // 9) ctx = O @ sa_out_w^T + b; out = LN(ctx + slots)
    sgemm_nt_bias<<<dim3(cH / GBN, BKR / GBM), 256>>>(g_ctx2, sa_out_w, sa_out_b, g_tmp, BKR, cH, cH);
    ln_residual_k<<<BKR, 256>>>(g_tmp, g_slots, on_g, on_b, out);
}